// round 9
// baseline (speedup 1.0000x reference)
#include <cuda_runtime.h>
#include <cuda_fp8.h>
#include <cstdint>

// Problem dims (fixed by reference)
#define M_DIM 16384
#define N_DIM 4096
#define K_DIM 4096

#define TILE_M 128
#define TILE_N 128
#define TILE_K 128           // 128 fp8 = 128 B per row (one SW128 atom row)
#define STAGES 3
#define NKT   (K_DIM / TILE_K)               // 32
#define NT_N  (N_DIM / TILE_N)               // 32
#define GRID_GEMM ((M_DIM / TILE_M) * NT_N)  // 4096

#define STAGE_BYTES (TILE_M * 128 + TILE_N * 128)        // 32 KB / stage
#define SM_BIAS  128
#define SM_TILES 1024
#define SM_RED   1024                                    // reused post-mainloop
#define SMEM_TOTAL (SM_TILES + STAGES * STAGE_BYTES)     // 99328 B

// W is pre-scaled by 64 into ~N(0,1) (avoids e4m3 subnormals); undo in epilogue
#define INV_SCALE (1.0f / 64.0f)

// Scratch (device statics — allocation-free per harness rules)
__device__ uint8_t g_xq[(size_t)M_DIM * K_DIM];          // 64 MB (e4m3)
__device__ uint8_t g_wq[(size_t)N_DIM * K_DIM];          // 16 MB (e4m3)
__device__ float g_pmax[(size_t)M_DIM * NT_N];           //  2 MB
__device__ float g_psum[(size_t)M_DIM * NT_N];           //  2 MB

__device__ __forceinline__ uint32_t smem_u32(const void* p) {
    uint32_t a;
    asm("{ .reg .u64 t; cvta.to.shared.u64 t, %1; cvt.u32.u64 %0, t; }" : "=r"(a) : "l"(p));
    return a;
}
__device__ __forceinline__ void cp16(uint32_t saddr, const void* g) {
    asm volatile("cp.async.cg.shared.global [%0], [%1], 16;" :: "r"(saddr), "l"(g));
}
__device__ __forceinline__ void cp_commit() { asm volatile("cp.async.commit_group;"); }
template <int N> __device__ __forceinline__ void cp_wait() {
    asm volatile("cp.async.wait_group %0;" :: "n"(N) : "memory");
}

#define LDSM4(R0, R1, R2, R3, addr)                                             \
    asm volatile("ldmatrix.sync.aligned.m8n8.x4.shared.b16 {%0,%1,%2,%3}, [%4];" \
                 : "=r"(R0), "=r"(R1), "=r"(R2), "=r"(R3) : "r"(addr))

#define MMA16832_FP8(d, a, b)                                                    \
    asm volatile(                                                                \
        "mma.sync.aligned.m16n8k32.row.col.f32.e4m3.e4m3.f32 "                   \
        "{%0,%1,%2,%3}, {%4,%5,%6,%7}, {%8,%9}, {%0,%1,%2,%3};"                  \
        : "+f"((d)[0]), "+f"((d)[1]), "+f"((d)[2]), "+f"((d)[3])                 \
        : "r"((a)[0]), "r"((a)[1]), "r"((a)[2]), "r"((a)[3]),                    \
          "r"((b)[0]), "r"((b)[1]))

// ---------------------------------------------------------------------------
// fp32 -> e4m3 quantization: both tensors in ONE launch, two branch-free loops
// (W scaled by 64 into ~N(0,1) to stay out of e4m3 subnormal range)
// ---------------------------------------------------------------------------
__device__ __forceinline__ void q8(const float* __restrict__ s, uint8_t* __restrict__ d,
                                   long long i, float scale) {
    float4 v0 = *reinterpret_cast<const float4*>(s + i);
    float4 v1 = *reinterpret_cast<const float4*>(s + i + 4);
    __nv_fp8x2_storage_t p0 = __nv_cvt_float2_to_fp8x2(
        make_float2(v0.x * scale, v0.y * scale), __NV_SATFINITE, __NV_E4M3);
    __nv_fp8x2_storage_t p1 = __nv_cvt_float2_to_fp8x2(
        make_float2(v0.z * scale, v0.w * scale), __NV_SATFINITE, __NV_E4M3);
    __nv_fp8x2_storage_t p2 = __nv_cvt_float2_to_fp8x2(
        make_float2(v1.x * scale, v1.y * scale), __NV_SATFINITE, __NV_E4M3);
    __nv_fp8x2_storage_t p3 = __nv_cvt_float2_to_fp8x2(
        make_float2(v1.z * scale, v1.w * scale), __NV_SATFINITE, __NV_E4M3);
    uint2 out;
    out.x = (uint32_t)p0 | ((uint32_t)p1 << 16);
    out.y = (uint32_t)p2 | ((uint32_t)p3 << 16);
    *reinterpret_cast<uint2*>(d + i) = out;
}

__global__ void quant2_kernel(const float* __restrict__ x, uint8_t* __restrict__ xd,
                              long long nx,
                              const float* __restrict__ w, uint8_t* __restrict__ wd,
                              long long nw) {
    const long long stride = (long long)gridDim.x * blockDim.x * 8;
    const long long base = ((long long)blockIdx.x * blockDim.x + threadIdx.x) * 8;
    for (long long i = base; i < nx; i += stride) q8(x, xd, i, 1.0f);
    for (long long i = base; i < nw; i += stride) q8(w, wd, i, 64.0f);
}

// ---------------------------------------------------------------------------
// e4m3 FP8 GEMM (mma.sync m16n8k32, f32 acc) + fused per-tile LSE partials.
// Structure identical to the verified R3 int8 kernel (same 1-byte fragment
// geometry and SW128 swizzle); only operand type / acc / dequant changed.
// ---------------------------------------------------------------------------
__global__ __launch_bounds__(256, 2)
void gemm_lse_kernel(const float* __restrict__ bvec) {
    extern __shared__ char smem[];
    const uint32_t sb = smem_u32(smem);
    const int tid = threadIdx.x;
    const int wid = tid >> 5;
    const int lane = tid & 31;
    const int warp_m = wid >> 2;     // 0..1  (64 rows each)
    const int warp_n = wid & 3;      // 0..3  (32 cols each)
    const int n_tile = blockIdx.x & (NT_N - 1);
    const int m_tile = blockIdx.x >> 5;

    if (tid < TILE_N)
        ((float*)(smem + SM_BIAS))[tid] = bvec[n_tile * TILE_N + tid];

    // ---- cp.async geometry: thread -> 16B chunk c of rows r0 + 32i ----
    const int c  = tid & 7;
    const int r0 = tid >> 3;                       // 0..31
    const uint8_t* gA0 = g_xq + (size_t)(m_tile * TILE_M + r0) * K_DIM + c * 16;
    const uint8_t* gB0 = g_wq + (size_t)(n_tile * TILE_N + r0) * K_DIM + c * 16;
    const uint32_t soff = (uint32_t)(r0 * 128 + ((c ^ (r0 & 7)) << 4));  // SW128

    auto load_stage = [&](int s, int kt) {
        const uint8_t* ga = gA0 + (size_t)kt * TILE_K;
        const uint8_t* gb = gB0 + (size_t)kt * TILE_K;
        uint32_t sa  = sb + SM_TILES + s * STAGE_BYTES + soff;
        uint32_t sbm = sa + TILE_M * 128;
        #pragma unroll
        for (int i = 0; i < 4; i++) cp16(sa  + i * 4096, ga + (size_t)i * 32 * K_DIM);
        #pragma unroll
        for (int i = 0; i < 4; i++) cp16(sbm + i * 4096, gb + (size_t)i * 32 * K_DIM);
        cp_commit();
    };

    // ---- ldmatrix lane geometry (identical mapping for A and B reads) ----
    const int lrow_off = ((lane >> 3) & 1) * 8 + (lane & 7);  // row within 16-row group
    const int lchunk   = (lane >> 4);                         // 0/1: chunk parity

    uint32_t arow_base[4]; int arow_sw[4];
    #pragma unroll
    for (int mt = 0; mt < 4; mt++) {
        int row = warp_m * 64 + mt * 16 + lrow_off;
        arow_base[mt] = (uint32_t)(row * 128);
        arow_sw[mt] = row & 7;
    }
    uint32_t brow_base[2]; int brow_sw[2];
    #pragma unroll
    for (int bb = 0; bb < 2; bb++) {
        int nrow = warp_n * 32 + bb * 16 + lrow_off;
        brow_base[bb] = (uint32_t)(nrow * 128);
        brow_sw[bb] = nrow & 7;
    }

    float acc[4][4][4];
    #pragma unroll
    for (int mt = 0; mt < 4; mt++)
        #pragma unroll
        for (int nt = 0; nt < 4; nt++)
            #pragma unroll
            for (int j = 0; j < 4; j++) acc[mt][nt][j] = 0.0f;

    load_stage(0, 0);
    load_stage(1, 1);

    for (int kiter = 0; kiter < NKT; kiter++) {
        cp_wait<1>();
        __syncthreads();
        if (kiter + 2 < NKT) load_stage((kiter + 2) % STAGES, kiter + 2);
        else cp_commit();   // empty group keeps wait_group count exact

        const uint32_t stA = sb + SM_TILES + (kiter % STAGES) * STAGE_BYTES;
        const uint32_t stB = stA + TILE_M * 128;

        #pragma unroll
        for (int ks = 0; ks < 4; ks++) {          // 4 x k32 = TILE_K
            uint32_t a[4][4];
            #pragma unroll
            for (int mt = 0; mt < 4; mt++) {
                uint32_t addr = stA + arow_base[mt] +
                                ((uint32_t)((ks * 2 + lchunk) ^ arow_sw[mt]) << 4);
                LDSM4(a[mt][0], a[mt][1], a[mt][2], a[mt][3], addr);
            }
            uint32_t b[4][2];
            #pragma unroll
            for (int bb = 0; bb < 2; bb++) {
                uint32_t addr = stB + brow_base[bb] +
                                ((uint32_t)((ks * 2 + lchunk) ^ brow_sw[bb]) << 4);
                LDSM4(b[2 * bb][0], b[2 * bb + 1][0], b[2 * bb][1], b[2 * bb + 1][1], addr);
            }
            #pragma unroll
            for (int mt = 0; mt < 4; mt++)
                #pragma unroll
                for (int nt = 0; nt < 4; nt++)
                    MMA16832_FP8(acc[mt][nt], a[mt], b[nt]);
        }
    }

    // ---- epilogue: descale + bias + online (max, sumexp) over 128 cols ----
    const float* bias = (const float*)(smem + SM_BIAS);
    const float NEG_INF = __int_as_float(0xff800000);
    float rowmax[8], rowsum[8];

    #pragma unroll
    for (int mt = 0; mt < 4; mt++) {
        #pragma unroll
        for (int rh = 0; rh < 2; rh++) {
            float v[8];
            #pragma unroll
            for (int nt = 0; nt < 4; nt++) {
                int col = warp_n * 32 + nt * 8 + (lane & 3) * 2;
                v[nt * 2 + 0] = fmaf(acc[mt][nt][rh * 2 + 0], INV_SCALE, bias[col]);
                v[nt * 2 + 1] = fmaf(acc[mt][nt][rh * 2 + 1], INV_SCALE, bias[col + 1]);
            }
            float m = NEG_INF;
            #pragma unroll
            for (int j = 0; j < 8; j++) m = fmaxf(m, v[j]);
            float s = 0.0f;
            #pragma unroll
            for (int j = 0; j < 8; j++) s += __expf(v[j] - m);
            #pragma unroll
            for (int off = 1; off <= 2; off <<= 1) {
                float om = __shfl_xor_sync(0xffffffffu, m, off);
                float os = __shfl_xor_sync(0xffffffffu, s, off);
                float nm = fmaxf(m, om);
                s = s * __expf(m - nm) + os * __expf(om - nm);
                m = nm;
            }
            rowmax[mt * 2 + rh] = m;
            rowsum[mt * 2 + rh] = s;
        }
    }

    __syncthreads();   // all warps done with stage smem; reuse it
    float2* red = (float2*)(smem + SM_RED);   // [128 rows][4 n-warps]
    if ((lane & 3) == 0) {
        #pragma unroll
        for (int mt = 0; mt < 4; mt++)
            #pragma unroll
            for (int rh = 0; rh < 2; rh++) {
                int rowl = warp_m * 64 + mt * 16 + rh * 8 + (lane >> 2);
                red[rowl * 4 + warp_n] = make_float2(rowmax[mt * 2 + rh],
                                                     rowsum[mt * 2 + rh]);
            }
    }
    __syncthreads();

    if (tid < TILE_M) {
        float m = NEG_INF, s = 0.0f;
        #pragma unroll
        for (int w = 0; w < 4; w++) {
            float2 p = red[tid * 4 + w];
            float nm = fmaxf(m, p.x);
            s = s * __expf(m - nm) + p.y * __expf(p.x - nm);
            m = nm;
        }
        const int row = m_tile * TILE_M + tid;
        g_pmax[(size_t)row * NT_N + n_tile] = m;
        g_psum[(size_t)row * NT_N + n_tile] = s;
    }
}

// ---------------------------------------------------------------------------
// Merge 32 (max, sumexp) partials per row; LeakyReLU^2 + exact GELU^2
// ---------------------------------------------------------------------------
__global__ void reduce_kernel(float* __restrict__ out) {
    const int row = blockIdx.x * blockDim.x + threadIdx.x;
    if (row >= M_DIM) return;
    const float* pm = g_pmax + (size_t)row * NT_N;
    const float* ps = g_psum + (size_t)row * NT_N;
    float gm = __int_as_float(0xff800000);
    #pragma unroll
    for (int t = 0; t < NT_N; t++) gm = fmaxf(gm, pm[t]);
    float s = 0.0f;
    #pragma unroll
    for (int t = 0; t < NT_N; t++) s += ps[t] * __expf(pm[t] - gm);
    float v = gm + logf(s);
    v = v > 0.0f ? v : 0.01f * v;
    v = v > 0.0f ? v : 0.01f * v;
    v = v * 0.5f * (1.0f + erff(v * 0.70710678118654752f));
    v = v * 0.5f * (1.0f + erff(v * 0.70710678118654752f));
    out[row] = v;
}

// ---------------------------------------------------------------------------
extern "C" void kernel_launch(void* const* d_in, const int* in_sizes, int n_in,
                              void* d_out, int out_size) {
    const float* x = (const float*)d_in[0];
    const float* W = (const float*)d_in[1];
    const float* b = (const float*)d_in[2];
    float* out = (float*)d_out;

    uint8_t *xq = nullptr, *wq = nullptr;
    cudaGetSymbolAddress((void**)&xq, g_xq);
    cudaGetSymbolAddress((void**)&wq, g_wq);

    quant2_kernel<<<8192, 256>>>(x, xq, (long long)M_DIM * K_DIM,
                                 W, wq, (long long)N_DIM * K_DIM);

    cudaFuncSetAttribute(gemm_lse_kernel,
                         cudaFuncAttributeMaxDynamicSharedMemorySize, SMEM_TOTAL);
    gemm_lse_kernel<<<GRID_GEMM, 256, SMEM_TOTAL>>>(b);

    reduce_kernel<<<(M_DIM + 255) / 256, 256>>>(out);
}

// round 10
// speedup vs baseline: 1.2021x; 1.2021x over previous
#include <cuda_runtime.h>
#include <cuda_bf16.h>
#include <cstdint>

// Problem dims (fixed by reference)
#define M_DIM 16384
#define N_DIM 4096
#define K_DIM 4096

#define TILE_M 128
#define TILE_N 128
#define TILE_K 64            // 64 bf16 = 128 B per row
#define STAGES 3
#define NKT   (K_DIM / TILE_K)               // 64
#define NT_N  (N_DIM / TILE_N)               // 32
#define GRID_GEMM ((M_DIM / TILE_M) * NT_N)  // 4096

#define STAGE_BYTES (TILE_M * 128 + TILE_N * 128)        // 32 KB / stage
#define SM_BIAS  128
#define SM_TILES 1024
#define SM_RED   1024                                    // reused post-mainloop
#define SMEM_TOTAL (SM_TILES + STAGES * STAGE_BYTES)     // 99328 B

// Scratch (device statics — allocation-free per harness rules)
__device__ __nv_bfloat16 g_xbf[(size_t)M_DIM * K_DIM];   // 128 MB
__device__ __nv_bfloat16 g_wbf[(size_t)N_DIM * K_DIM];   //  32 MB
__device__ float g_pmax[(size_t)M_DIM * NT_N];           //   2 MB
__device__ float g_psum[(size_t)M_DIM * NT_N];           //   2 MB

__device__ __forceinline__ uint32_t smem_u32(const void* p) {
    uint32_t a;
    asm("{ .reg .u64 t; cvta.to.shared.u64 t, %1; cvt.u32.u64 %0, t; }" : "=r"(a) : "l"(p));
    return a;
}
__device__ __forceinline__ void cp16(uint32_t saddr, const void* g) {
    asm volatile("cp.async.cg.shared.global [%0], [%1], 16;" :: "r"(saddr), "l"(g));
}
__device__ __forceinline__ void cp_commit() { asm volatile("cp.async.commit_group;"); }
template <int N> __device__ __forceinline__ void cp_wait() {
    asm volatile("cp.async.wait_group %0;" :: "n"(N) : "memory");
}

#define LDSM4(R0, R1, R2, R3, addr)                                             \
    asm volatile("ldmatrix.sync.aligned.m8n8.x4.shared.b16 {%0,%1,%2,%3}, [%4];" \
                 : "=r"(R0), "=r"(R1), "=r"(R2), "=r"(R3) : "r"(addr))

#define MMA16816(d, a, b)                                                        \
    asm volatile(                                                                \
        "mma.sync.aligned.m16n8k16.row.col.f32.bf16.bf16.f32 "                   \
        "{%0,%1,%2,%3}, {%4,%5,%6,%7}, {%8,%9}, {%0,%1,%2,%3};"                  \
        : "+f"((d)[0]), "+f"((d)[1]), "+f"((d)[2]), "+f"((d)[3])                 \
        : "r"((a)[0]), "r"((a)[1]), "r"((a)[2]), "r"((a)[3]),                    \
          "r"((b)[0]), "r"((b)[1]))

// ---------------------------------------------------------------------------
// fp32 -> bf16 conversion: both tensors in ONE launch.
// 8 floats / iter: two float4 streaming loads -> one 16B store.
// ---------------------------------------------------------------------------
__device__ __forceinline__ void cvt8(const float* __restrict__ s,
                                     __nv_bfloat16* __restrict__ d, long long i) {
    float4 v0 = __ldcs(reinterpret_cast<const float4*>(s + i));
    float4 v1 = __ldcs(reinterpret_cast<const float4*>(s + i + 4));
    __nv_bfloat162 p0 = __floats2bfloat162_rn(v0.x, v0.y);
    __nv_bfloat162 p1 = __floats2bfloat162_rn(v0.z, v0.w);
    __nv_bfloat162 p2 = __floats2bfloat162_rn(v1.x, v1.y);
    __nv_bfloat162 p3 = __floats2bfloat162_rn(v1.z, v1.w);
    uint4 o;
    o.x = *reinterpret_cast<uint32_t*>(&p0);
    o.y = *reinterpret_cast<uint32_t*>(&p1);
    o.z = *reinterpret_cast<uint32_t*>(&p2);
    o.w = *reinterpret_cast<uint32_t*>(&p3);
    *reinterpret_cast<uint4*>(d + i) = o;
}

__global__ void cvt2_kernel(const float* __restrict__ x, __nv_bfloat16* __restrict__ xd,
                            long long nx,
                            const float* __restrict__ w, __nv_bfloat16* __restrict__ wd,
                            long long nw) {
    const long long stride = (long long)gridDim.x * blockDim.x * 8;
    const long long base = ((long long)blockIdx.x * blockDim.x + threadIdx.x) * 8;
    for (long long i = base; i < nx; i += stride) cvt8(x, xd, i);
    for (long long i = base; i < nw; i += stride) cvt8(w, wd, i);
}

// ---------------------------------------------------------------------------
// bf16 HMMA GEMM (mma.sync m16n8k16) + fused per-tile logsumexp partials.
// Byte-identical to the proven 1197.8us R7 kernel. FROZEN.
// ---------------------------------------------------------------------------
__global__ __launch_bounds__(256, 2)
void gemm_lse_kernel(const float* __restrict__ bvec) {
    extern __shared__ char smem[];
    const uint32_t sb = smem_u32(smem);
    const int tid = threadIdx.x;
    const int wid = tid >> 5;
    const int lane = tid & 31;
    const int warp_m = wid >> 2;     // 0..1
    const int warp_n = wid & 3;      // 0..3
    const int n_tile = blockIdx.x & (NT_N - 1);
    const int m_tile = blockIdx.x >> 5;

    if (tid < TILE_N)
        ((float*)(smem + SM_BIAS))[tid] = bvec[n_tile * TILE_N + tid];

    // ---- load geometry (cp.async): thread -> chunk c of rows r0 + 32i ----
    const int c  = tid & 7;
    const int r0 = tid >> 3;                       // 0..31
    const size_t gA0 = (size_t)(m_tile * TILE_M + r0) * K_DIM + c * 8;
    const size_t gB0 = (size_t)(n_tile * TILE_N + r0) * K_DIM + c * 8;
    const uint32_t soff = (uint32_t)(r0 * 128 + ((c ^ (r0 & 7)) << 4));  // SW128

    auto load_stage = [&](int s, int kt) {
        const __nv_bfloat16* ga = g_xbf + gA0 + (size_t)kt * TILE_K;
        const __nv_bfloat16* gb = g_wbf + gB0 + (size_t)kt * TILE_K;
        uint32_t sa  = sb + SM_TILES + s * STAGE_BYTES + soff;
        uint32_t sbm = sa + TILE_M * 128;
        #pragma unroll
        for (int i = 0; i < 4; i++) cp16(sa  + i * 4096, ga + (size_t)i * 32 * K_DIM);
        #pragma unroll
        for (int i = 0; i < 4; i++) cp16(sbm + i * 4096, gb + (size_t)i * 32 * K_DIM);
        cp_commit();
    };

    // ---- ldmatrix geometry ----
    const int arow_l = (lane & 15);
    const int acb    = (lane >> 4);                // 0/1
    uint32_t arow_base[4];
    int      arow_sw[4];
    #pragma unroll
    for (int mt = 0; mt < 4; mt++) {
        int row = warp_m * 64 + mt * 16 + arow_l;
        arow_base[mt] = (uint32_t)(row * 128);
        arow_sw[mt] = row & 7;
    }
    const int brow_l = ((lane >> 4) << 3) + (lane & 7);  // 0..15
    const int bpar   = (lane >> 3) & 1;
    uint32_t brow_base[2];
    int      brow_sw[2];
    #pragma unroll
    for (int bb = 0; bb < 2; bb++) {
        int nrow = warp_n * 32 + bb * 16 + brow_l;
        brow_base[bb] = (uint32_t)(nrow * 128);
        brow_sw[bb] = nrow & 7;
    }

    float acc[4][4][4];
    #pragma unroll
    for (int mt = 0; mt < 4; mt++)
        #pragma unroll
        for (int nt = 0; nt < 4; nt++)
            #pragma unroll
            for (int j = 0; j < 4; j++) acc[mt][nt][j] = 0.0f;

    // prefetch stages 0,1
    load_stage(0, 0);
    load_stage(1, 1);

    for (int kiter = 0; kiter < NKT; kiter++) {
        cp_wait<1>();
        __syncthreads();
        // issue next load (or empty group to keep wait_group count exact)
        if (kiter + 2 < NKT) load_stage((kiter + 2) % STAGES, kiter + 2);
        else cp_commit();

        const uint32_t stA = sb + SM_TILES + (kiter % STAGES) * STAGE_BYTES;
        const uint32_t stB = stA + TILE_M * 128;

        #pragma unroll
        for (int ks = 0; ks < 4; ks++) {
            uint32_t a[4][4];
            #pragma unroll
            for (int mt = 0; mt < 4; mt++) {
                uint32_t addr = stA + arow_base[mt] +
                                ((uint32_t)((ks * 2 + acb) ^ arow_sw[mt]) << 4);
                LDSM4(a[mt][0], a[mt][1], a[mt][2], a[mt][3], addr);
            }
            uint32_t b[4][2];
            #pragma unroll
            for (int bb = 0; bb < 2; bb++) {
                uint32_t addr = stB + brow_base[bb] +
                                ((uint32_t)((ks * 2 + bpar) ^ brow_sw[bb]) << 4);
                LDSM4(b[2 * bb][0], b[2 * bb][1], b[2 * bb + 1][0], b[2 * bb + 1][1], addr);
            }
            #pragma unroll
            for (int mt = 0; mt < 4; mt++)
                #pragma unroll
                for (int nt = 0; nt < 4; nt++)
                    MMA16816(acc[mt][nt], a[mt], b[nt]);
        }
    }

    // ---- epilogue: bias + online (max, sumexp) over this CTA's 128 cols ----
    const float* bias = (const float*)(smem + SM_BIAS);
    const float NEG_INF = __int_as_float(0xff800000);
    float rowmax[8], rowsum[8];

    #pragma unroll
    for (int mt = 0; mt < 4; mt++) {
        #pragma unroll
        for (int rh = 0; rh < 2; rh++) {
            float v[8];
            #pragma unroll
            for (int nt = 0; nt < 4; nt++) {
                int col = warp_n * 32 + nt * 8 + (lane & 3) * 2;
                v[nt * 2 + 0] = acc[mt][nt][rh * 2 + 0] + bias[col];
                v[nt * 2 + 1] = acc[mt][nt][rh * 2 + 1] + bias[col + 1];
            }
            float m = NEG_INF;
            #pragma unroll
            for (int j = 0; j < 8; j++) m = fmaxf(m, v[j]);
            float s = 0.0f;
            #pragma unroll
            for (int j = 0; j < 8; j++) s += __expf(v[j] - m);
            // merge across the 4 lanes sharing this row
            #pragma unroll
            for (int off = 1; off <= 2; off <<= 1) {
                float om = __shfl_xor_sync(0xffffffffu, m, off);
                float os = __shfl_xor_sync(0xffffffffu, s, off);
                float nm = fmaxf(m, om);
                s = s * __expf(m - nm) + os * __expf(om - nm);
                m = nm;
            }
            rowmax[mt * 2 + rh] = m;
            rowsum[mt * 2 + rh] = s;
        }
    }

    __syncthreads();   // all warps done with stage smem; reuse it
    float2* red = (float2*)(smem + SM_RED);   // [128 rows][4 n-warps]
    if ((lane & 3) == 0) {
        #pragma unroll
        for (int mt = 0; mt < 4; mt++)
            #pragma unroll
            for (int rh = 0; rh < 2; rh++) {
                int rowl = warp_m * 64 + mt * 16 + rh * 8 + (lane >> 2);
                red[rowl * 4 + warp_n] = make_float2(rowmax[mt * 2 + rh],
                                                     rowsum[mt * 2 + rh]);
            }
    }
    __syncthreads();

    if (tid < TILE_M) {
        float m = NEG_INF, s = 0.0f;
        #pragma unroll
        for (int w = 0; w < 4; w++) {
            float2 p = red[tid * 4 + w];
            float nm = fmaxf(m, p.x);
            s = s * __expf(m - nm) + p.y * __expf(p.x - nm);
            m = nm;
        }
        const int row = m_tile * TILE_M + tid;
        g_pmax[(size_t)row * NT_N + n_tile] = m;
        g_psum[(size_t)row * NT_N + n_tile] = s;
    }
}

// ---------------------------------------------------------------------------
// Warp-per-row merge of 32 (max, sumexp) partials; LeakyReLU^2 + GELU^2.
// Lane t holds partial t -> coalesced loads + shfl tree reduction.
// ---------------------------------------------------------------------------
__global__ void reduce_kernel(float* __restrict__ out) {
    const int gt   = blockIdx.x * blockDim.x + threadIdx.x;
    const int row  = gt >> 5;
    const int lane = gt & 31;
    if (row >= M_DIM) return;
    float m = g_pmax[(size_t)row * NT_N + lane];
    float s = g_psum[(size_t)row * NT_N + lane];
    #pragma unroll
    for (int off = 16; off >= 1; off >>= 1) {
        float om = __shfl_xor_sync(0xffffffffu, m, off);
        float os = __shfl_xor_sync(0xffffffffu, s, off);
        float nm = fmaxf(m, om);
        s = s * __expf(m - nm) + os * __expf(om - nm);
        m = nm;
    }
    if (lane == 0) {
        float v = m + logf(s);
        v = v > 0.0f ? v : 0.01f * v;
        v = v > 0.0f ? v : 0.01f * v;
        v = v * 0.5f * (1.0f + erff(v * 0.70710678118654752f));
        v = v * 0.5f * (1.0f + erff(v * 0.70710678118654752f));
        out[row] = v;
    }
}

// ---------------------------------------------------------------------------
extern "C" void kernel_launch(void* const* d_in, const int* in_sizes, int n_in,
                              void* d_out, int out_size) {
    const float* x = (const float*)d_in[0];
    const float* W = (const float*)d_in[1];
    const float* b = (const float*)d_in[2];
    float* out = (float*)d_out;

    __nv_bfloat16 *xbf = nullptr, *wbf = nullptr;
    cudaGetSymbolAddress((void**)&xbf, g_xbf);
    cudaGetSymbolAddress((void**)&wbf, g_wbf);

    cvt2_kernel<<<8192, 256>>>(x, xbf, (long long)M_DIM * K_DIM,
                               W, wbf, (long long)N_DIM * K_DIM);

    cudaFuncSetAttribute(gemm_lse_kernel,
                         cudaFuncAttributeMaxDynamicSharedMemorySize, SMEM_TOTAL);
    gemm_lse_kernel<<<GRID_GEMM, 256, SMEM_TOTAL>>>(b);

    // one warp per row: 16384 rows * 32 lanes / 256 threads = 2048 blocks
    reduce_kernel<<<(M_DIM * 32) / 256, 256>>>(out);
}